// round 9
// baseline (speedup 1.0000x reference)
#include <cuda_runtime.h>
#include <cuda_fp16.h>
#include <cstdint>

// Problem constants (fixed by the reference)
#define BB   8
#define KK   100000
#define CC   16
#define OO   16
#define HH   512
#define WW   512
#define NNODES (BB * KK)          // 800000
#define NPIX_B (HH * WW)          // 262144
#define ALPHA_PRIOR 1.0f

// Scratch grid: fp16 half-planar [half][batch][H*W], 4 x half2 = 8 channels = 16B
// per pixel-half. 67 MB total -> L2-resident.
__device__ uint4 g_grid[2][BB][NPIX_B];
// Staging: transformed node values, fp16, [half][node] = 16B each (26 MB).
__device__ uint4 g_y[2][NNODES];

// ---------------------------------------------------------------------------
// Kernel 1: transform — per-node 16x16 matvec (fp32), type-selected weights,
// fp16 pack, sequential 2x16B store. Pure streaming, no atomics.
// ---------------------------------------------------------------------------
__device__ __forceinline__ float dot16(const float* w,
                                       float4 f0, float4 f1, float4 f2, float4 f3) {
    const float4* w4 = (const float4*)w;
    float4 w0 = w4[0], w1 = w4[1], w2 = w4[2], w3 = w4[3];
    return w0.x * f0.x + w0.y * f0.y + w0.z * f0.z + w0.w * f0.w
         + w1.x * f1.x + w1.y * f1.y + w1.z * f1.z + w1.w * f1.w
         + w2.x * f2.x + w2.y * f2.y + w2.z * f2.z + w2.w * f2.w
         + w3.x * f3.x + w3.y * f3.y + w3.z * f3.z + w3.w * f3.w;
}

__device__ __forceinline__ unsigned pack_h2(float a, float b) {
    __half2 h = __floats2half2_rn(a, b);
    return *reinterpret_cast<unsigned*>(&h);
}

__global__ __launch_bounds__(256) void transform_kernel(
    const float* __restrict__ node_feat,   // [B,K,C]
    const int*   __restrict__ node_types,  // [B,K]
    const float* __restrict__ w_obj,       // [O,C]
    const float* __restrict__ w_prior)     // [O,C]
{
    __shared__ float sw[2][OO * CC];       // [type][o*16+c]
    int tid = threadIdx.x;
    if (tid < OO * CC) {
        sw[0][tid] = w_obj[tid];
        sw[1][tid] = ALPHA_PRIOR * w_prior[tid];
    }
    __syncthreads();

    int n = blockIdx.x * 256 + tid;
    if (n >= NNODES) return;

    const float4* f4 = (const float4*)(node_feat + (size_t)n * CC);
    float4 f0 = f4[0], f1 = f4[1], f2 = f4[2], f3 = f4[3];
    int t = node_types[n] & 1;
    const float* wbase = sw[t];

    float v[16];
    #pragma unroll
    for (int o = 0; o < 16; o++)
        v[o] = dot16(wbase + o * CC, f0, f1, f2, f3);

    #pragma unroll
    for (int h = 0; h < 2; h++) {
        uint4 p;
        p.x = pack_h2(v[8*h + 0], v[8*h + 1]);
        p.y = pack_h2(v[8*h + 2], v[8*h + 3]);
        p.z = pack_h2(v[8*h + 4], v[8*h + 5]);
        p.w = pack_h2(v[8*h + 6], v[8*h + 7]);
        g_y[h][n] = p;
    }
}

// ---------------------------------------------------------------------------
// Kernel 2: splat — coalesced 32B reload of transformed values, 2x red.v4.f16x2
// into the pixel grid. Minimal instruction count: exposes pure atomic cost.
// ---------------------------------------------------------------------------
__global__ __launch_bounds__(256) void splat_kernel(
    const float* __restrict__ node_xy)     // [B,K,2]
{
    int n = blockIdx.x * 256 + threadIdx.x;
    if (n >= NNODES) return;
    int b = n / KK;

    float2 xy = ((const float2*)node_xy)[n];
    // jnp.round == round-half-to-even == rintf; clip to [0, 511]
    int ix = (int)fminf(fmaxf(rintf(xy.x), 0.f), (float)(WW - 1));
    int iy = (int)fminf(fmaxf(rintf(xy.y), 0.f), (float)(HH - 1));
    int pix = iy * WW + ix;

    uint4 y0 = g_y[0][n];
    uint4 y1 = g_y[1][n];
    uint4* d0 = &g_grid[0][b][pix];
    uint4* d1 = &g_grid[1][b][pix];
    asm volatile("red.global.add.noftz.v4.f16x2 [%0], {%1, %2, %3, %4};"
                 :: "l"(d0), "r"(y0.x), "r"(y0.y), "r"(y0.z), "r"(y0.w) : "memory");
    asm volatile("red.global.add.noftz.v4.f16x2 [%0], {%1, %2, %3, %4};"
                 :: "l"(d1), "r"(y1.x), "r"(y1.y), "r"(y1.z), "r"(y1.w) : "memory");
}

// ---------------------------------------------------------------------------
// Kernel 3: conv — depthwise 3x3 over fp16 half-planes (fp32 math), NCHW fp32
// writeout. Thread: one x, one channel-half (8 ch), strip of 4 y rows.
// Grid = (8, 128, 8) = 8192 blocks. (Unchanged from R8: 39.9 us, characterized.)
// ---------------------------------------------------------------------------
__global__ __launch_bounds__(128) void conv_kernel(float* __restrict__ out) {
    int lane = threadIdx.x & 31;
    int w    = threadIdx.x >> 5;               // 0..3
    int h    = w & 1;                          // channel-half
    int x    = blockIdx.x * 64 + (w >> 1) * 32 + lane;  // 0..511
    int y0   = blockIdx.y * 4;                 // strip start
    int b    = blockIdx.z;

    const uint4* plane = g_grid[h][b];
    const uint4 z16 = make_uint4(0u, 0u, 0u, 0u);

    float acc[4][8];
    #pragma unroll
    for (int j = 0; j < 4; j++)
        #pragma unroll
        for (int i = 0; i < 8; i++) acc[j][i] = 0.f;

    #pragma unroll
    for (int r = 0; r < 6; r++) {
        int yy = y0 - 1 + r;
        if ((unsigned)yy >= HH) continue;      // y zero-pad

        const uint4* row = plane + (size_t)yy * WW;
        uint4 cq = __ldg(row + x);
        uint4 lq = (x > 0)      ? __ldg(row + x - 1) : z16;
        uint4 rq = (x < WW - 1) ? __ldg(row + x + 1) : z16;

        const __half2* ch = (const __half2*)&cq;
        const __half2* lh = (const __half2*)&lq;
        const __half2* rh = (const __half2*)&rq;

        float u[8], v[8];
        #pragma unroll
        for (int j = 0; j < 4; j++) {
            float2 cf = __half22float2(ch[j]);
            float2 lf = __half22float2(lh[j]);
            float2 rf = __half22float2(rh[j]);
            float sx = lf.x + rf.x, sy = lf.y + rf.y;
            u[2*j+0] = 0.075f * sx + 0.125f * cf.x;
            u[2*j+1] = 0.075f * sy + 0.125f * cf.y;
            v[2*j+0] = 0.125f * sx + 0.300f * cf.x;
            v[2*j+1] = 0.125f * sy + 0.300f * cf.y;
        }

        #pragma unroll
        for (int j = 0; j < 4; j++) {
            int d = (r - 1) - j;               // input row offset from output row
            if (d == 0) {
                #pragma unroll
                for (int i = 0; i < 8; i++) acc[j][i] += v[i];
            } else if (d == 1 || d == -1) {
                #pragma unroll
                for (int i = 0; i < 8; i++) acc[j][i] += u[i];
            }
        }
    }

    // NCHW writeout: channels o = 8h..8h+7. Warp-coalesced streaming stores.
    const size_t plane_out = (size_t)HH * WW;
    size_t base = ((size_t)b * OO + h * 8) * plane_out + (size_t)y0 * WW + x;
    #pragma unroll
    for (int i = 0; i < 8; i++)
        #pragma unroll
        for (int j = 0; j < 4; j++)
            __stcs(&out[base + (size_t)i * plane_out + (size_t)j * WW], acc[j][i]);
}

// ---------------------------------------------------------------------------
// Launch: memset(67 MB) -> transform -> splat -> conv.
// Inputs: node_feat, node_xy, hw(int64, unused), node_types, w_obj, w_prior.
// ---------------------------------------------------------------------------
extern "C" void kernel_launch(void* const* d_in, const int* in_sizes, int n_in,
                              void* d_out, int out_size) {
    const float* node_feat  = (const float*)d_in[0];
    const float* node_xy    = (const float*)d_in[1];
    const int*   node_types = (const int*)d_in[3];
    const float* w_obj      = (const float*)d_in[4];
    const float* w_prior    = (const float*)d_in[5];
    float* out = (float*)d_out;

    static void* grid_ptr = nullptr;
    if (!grid_ptr) cudaGetSymbolAddress(&grid_ptr, g_grid);

    const size_t grid_bytes = sizeof(uint4) * 2ull * BB * NPIX_B;  // 67 MB

    cudaMemsetAsync(grid_ptr, 0, grid_bytes, 0);
    transform_kernel<<<(NNODES + 255) / 256, 256>>>(node_feat, node_types,
                                                    w_obj, w_prior);
    splat_kernel<<<(NNODES + 255) / 256, 256>>>(node_xy);
    dim3 conv_grid(WW / 64, HH / 4, BB);       // (8, 128, 8) = 8192 blocks
    conv_kernel<<<conv_grid, 128>>>(out);
}

// round 10
// speedup vs baseline: 1.0256x; 1.0256x over previous
#include <cuda_runtime.h>
#include <cuda_fp16.h>
#include <cstdint>

// Problem constants (fixed by the reference)
#define BB   8
#define KK   100000
#define CC   16
#define OO   16
#define HH   512
#define WW   512
#define NNODES (BB * KK)          // 800000
#define NPIX_B (HH * WW)          // 262144
#define ALPHA_PRIOR 1.0f

#define TITER  16                 // node-pairs per warp in transform
#define TBLK   256                // transform block size (8 warps)
#define TGRID  (NNODES / (2 * TITER * (TBLK / 32)))   // 3125 blocks
#define GRID_U4 ((size_t)2 * BB * NPIX_B)             // 4,194,304 uint4

// Scratch grid: fp16 half-planar [half][batch][H*W], 4 x half2 = 8 ch = 16B per
// pixel-half. 67 MB -> L2-resident. Zero-initialized at load; re-zeroed by
// transform_kernel each call.
__device__ uint4 g_grid[2][BB][NPIX_B];
// Staging: transformed node values, fp16 [node][16ch] (26 MB).
__device__ __half g_y[(size_t)NNODES * OO];

// ---------------------------------------------------------------------------
// Kernel 1: transform — warp-cooperative 16x16 matvec, weights in registers,
// features broadcast by shuffle. Also re-zeroes the pixel grid (fused memset).
// Warp step: 2 nodes. Lane l: output o=l&15 of node-half l>>4.
// ---------------------------------------------------------------------------
__global__ __launch_bounds__(TBLK) void transform_kernel(
    const float* __restrict__ node_feat,   // [B,K,C]
    const int*   __restrict__ node_types,  // [B,K]
    const float* __restrict__ w_obj,       // [O,C]
    const float* __restrict__ w_prior)     // [O,C]
{
    int lane = threadIdx.x & 31;
    int wid  = threadIdx.x >> 5;
    int o    = lane & 15;
    int half = lane >> 4;

    // Both weight rows for this lane's output, loaded once per warp.
    float wo[16], wp[16];
    #pragma unroll
    for (int c = 0; c < 16; c++) {
        wo[c] = __ldg(&w_obj[o * CC + c]);
        wp[c] = ALPHA_PRIOR * __ldg(&w_prior[o * CC + c]);
    }

    int base = (blockIdx.x * (TBLK / 32) + wid) * (2 * TITER);  // warp's 1st node

    #pragma unroll 2
    for (int it = 0; it < TITER; it++) {
        int nb = base + it * 2;                     // nodes nb, nb+1
        // Coalesced: lane l reads feature (c = l&15) of node nb + (l>>4).
        float f = __ldg(&node_feat[(size_t)nb * CC + lane]);
        int t = __ldg(&node_types[nb + half]) & 1;

        float vo = 0.f, vp = 0.f;
        #pragma unroll
        for (int c = 0; c < 16; c++) {
            float fc = __shfl_sync(0xffffffffu, f, (half << 4) | c);
            vo = fmaf(wo[c], fc, vo);
            vp = fmaf(wp[c], fc, vp);
        }
        float v = t ? vp : vo;
        // g_y[(nb+half)*16 + o] == g_y[nb*16 + lane]: 64B contiguous per warp.
        g_y[(size_t)nb * OO + lane] = __float2half_rn(v);
    }

    // Fused grid zeroing (L2-absorbed; must complete before splat_kernel,
    // which is guaranteed by the kernel boundary).
    uint4* gz = (uint4*)g_grid;
    const uint4 z = make_uint4(0u, 0u, 0u, 0u);
    for (size_t i = (size_t)blockIdx.x * TBLK + threadIdx.x; i < GRID_U4;
         i += (size_t)TGRID * TBLK)
        gz[i] = z;
}

// ---------------------------------------------------------------------------
// Kernel 2: splat — coalesced 32B reload of transformed values, 2x red.v4.f16x2
// into the pixel grid (L2-hit atomics).
// ---------------------------------------------------------------------------
__global__ __launch_bounds__(256) void splat_kernel(
    const float* __restrict__ node_xy)     // [B,K,2]
{
    int n = blockIdx.x * 256 + threadIdx.x;
    if (n >= NNODES) return;
    int b = n / KK;

    float2 xy = ((const float2*)node_xy)[n];
    // jnp.round == round-half-to-even == rintf; clip to [0, 511]
    int ix = (int)fminf(fmaxf(rintf(xy.x), 0.f), (float)(WW - 1));
    int iy = (int)fminf(fmaxf(rintf(xy.y), 0.f), (float)(HH - 1));
    int pix = iy * WW + ix;

    const uint4* yv = (const uint4*)g_y;
    uint4 y0 = __ldg(&yv[(size_t)n * 2 + 0]);   // ch 0-7
    uint4 y1 = __ldg(&yv[(size_t)n * 2 + 1]);   // ch 8-15
    uint4* d0 = &g_grid[0][b][pix];
    uint4* d1 = &g_grid[1][b][pix];
    asm volatile("red.global.add.noftz.v4.f16x2 [%0], {%1, %2, %3, %4};"
                 :: "l"(d0), "r"(y0.x), "r"(y0.y), "r"(y0.z), "r"(y0.w) : "memory");
    asm volatile("red.global.add.noftz.v4.f16x2 [%0], {%1, %2, %3, %4};"
                 :: "l"(d1), "r"(y1.x), "r"(y1.y), "r"(y1.z), "r"(y1.w) : "memory");
}

// ---------------------------------------------------------------------------
// Kernel 3: conv — depthwise 3x3 over fp16 half-planes (fp32 math), NCHW fp32
// writeout. Thread: one x, one channel-half (8 ch), strip of 4 y rows.
// Grid = (8, 128, 8) = 8192 blocks.
// ---------------------------------------------------------------------------
__global__ __launch_bounds__(128) void conv_kernel(float* __restrict__ out) {
    int lane = threadIdx.x & 31;
    int w    = threadIdx.x >> 5;               // 0..3
    int h    = w & 1;                          // channel-half
    int x    = blockIdx.x * 64 + (w >> 1) * 32 + lane;  // 0..511
    int y0   = blockIdx.y * 4;                 // strip start
    int b    = blockIdx.z;

    const uint4* plane = g_grid[h][b];
    const uint4 z16 = make_uint4(0u, 0u, 0u, 0u);

    float acc[4][8];
    #pragma unroll
    for (int j = 0; j < 4; j++)
        #pragma unroll
        for (int i = 0; i < 8; i++) acc[j][i] = 0.f;

    #pragma unroll
    for (int r = 0; r < 6; r++) {
        int yy = y0 - 1 + r;
        if ((unsigned)yy >= HH) continue;      // y zero-pad

        const uint4* row = plane + (size_t)yy * WW;
        uint4 cq = __ldg(row + x);
        uint4 lq = (x > 0)      ? __ldg(row + x - 1) : z16;
        uint4 rq = (x < WW - 1) ? __ldg(row + x + 1) : z16;

        const __half2* ch = (const __half2*)&cq;
        const __half2* lh = (const __half2*)&lq;
        const __half2* rh = (const __half2*)&rq;

        float u[8], v[8];
        #pragma unroll
        for (int j = 0; j < 4; j++) {
            float2 cf = __half22float2(ch[j]);
            float2 lf = __half22float2(lh[j]);
            float2 rf = __half22float2(rh[j]);
            float sx = lf.x + rf.x, sy = lf.y + rf.y;
            u[2*j+0] = 0.075f * sx + 0.125f * cf.x;
            u[2*j+1] = 0.075f * sy + 0.125f * cf.y;
            v[2*j+0] = 0.125f * sx + 0.300f * cf.x;
            v[2*j+1] = 0.125f * sy + 0.300f * cf.y;
        }

        #pragma unroll
        for (int j = 0; j < 4; j++) {
            int d = (r - 1) - j;               // input row offset from output row
            if (d == 0) {
                #pragma unroll
                for (int i = 0; i < 8; i++) acc[j][i] += v[i];
            } else if (d == 1 || d == -1) {
                #pragma unroll
                for (int i = 0; i < 8; i++) acc[j][i] += u[i];
            }
        }
    }

    // NCHW writeout: channels o = 8h..8h+7. Warp-coalesced streaming stores.
    const size_t plane_out = (size_t)HH * WW;
    size_t base = ((size_t)b * OO + h * 8) * plane_out + (size_t)y0 * WW + x;
    #pragma unroll
    for (int i = 0; i < 8; i++)
        #pragma unroll
        for (int j = 0; j < 4; j++)
            __stcs(&out[base + (size_t)i * plane_out + (size_t)j * WW], acc[j][i]);
}

// ---------------------------------------------------------------------------
// Launch: transform(+zero) -> splat -> conv. 3 launches total.
// Inputs: node_feat, node_xy, hw(int64, unused), node_types, w_obj, w_prior.
// ---------------------------------------------------------------------------
extern "C" void kernel_launch(void* const* d_in, const int* in_sizes, int n_in,
                              void* d_out, int out_size) {
    const float* node_feat  = (const float*)d_in[0];
    const float* node_xy    = (const float*)d_in[1];
    const int*   node_types = (const int*)d_in[3];
    const float* w_obj      = (const float*)d_in[4];
    const float* w_prior    = (const float*)d_in[5];
    float* out = (float*)d_out;

    transform_kernel<<<TGRID, TBLK>>>(node_feat, node_types, w_obj, w_prior);
    splat_kernel<<<(NNODES + 255) / 256, 256>>>(node_xy);
    dim3 conv_grid(WW / 64, HH / 4, BB);       // (8, 128, 8) = 8192 blocks
    conv_kernel<<<conv_grid, 128>>>(out);
}

// round 11
// speedup vs baseline: 1.5256x; 1.4875x over previous
#include <cuda_runtime.h>
#include <cuda_fp16.h>
#include <cstdint>

// Problem constants (fixed by the reference)
#define BB   8
#define KK   100000
#define CC   16
#define OO   16
#define HH   512
#define WW   512
#define NNODES (BB * KK)          // 800000
#define NPIX_B (HH * WW)          // 262144
#define ALPHA_PRIOR 1.0f

#define GROUPS  (NNODES / 16)     // 50000 groups of 16 nodes
#define GITER   10                // groups per warp
#define TBLK    256               // 8 warps
#define TGRID   (GROUPS / (GITER * (TBLK / 32)))      // 625 blocks
#define GRID_U4 ((size_t)2 * BB * NPIX_B)             // 4,194,304 uint4

// Scratch grid: fp16 half-planar [half][batch][H*W], 4 x half2 = 8 ch = 16B per
// pixel-half. 67 MB -> L2-resident. Re-zeroed inside transform_kernel each call.
__device__ uint4 g_grid[2][BB][NPIX_B];
// Staging: transformed node values, fp16 [node][16ch] (26 MB).
__device__ __half g_y[(size_t)NNODES * OO];

// ---------------------------------------------------------------------------
// Helpers
// ---------------------------------------------------------------------------
__device__ __forceinline__ unsigned f2h2(float a, float b) {
    __half2 h = __floats2half2_rn(a, b);
    return *reinterpret_cast<unsigned*>(&h);
}

__device__ __forceinline__ void mma16816(float d[4],
                                         const unsigned a[4],
                                         const unsigned b0, const unsigned b1) {
    asm volatile(
        "mma.sync.aligned.m16n8k16.row.col.f32.f16.f16.f32 "
        "{%0,%1,%2,%3}, {%4,%5,%6,%7}, {%8,%9}, {%10,%11,%12,%13};"
        : "=f"(d[0]), "=f"(d[1]), "=f"(d[2]), "=f"(d[3])
        : "r"(a[0]), "r"(a[1]), "r"(a[2]), "r"(a[3]),
          "r"(b0), "r"(b1),
          "f"(0.f), "f"(0.f), "f"(0.f), "f"(0.f));
}

// ---------------------------------------------------------------------------
// Kernel 1: transform — tensor-core 16x16 matvec batch.
// Warp step: 16 nodes. A = F[16 nodes][16 feats] fp16 (direct gmem gather),
// B = W^T fragments (held in regs, loaded once), 4x HMMA -> Y_obj, Y_prior
// fp32, per-row type select, fp16 pack, store. Also re-zeroes the pixel grid.
// ---------------------------------------------------------------------------
__global__ __launch_bounds__(TBLK) void transform_kernel(
    const float* __restrict__ node_feat,   // [B,K,C]
    const int*   __restrict__ node_types,  // [B,K]
    const float* __restrict__ w_obj,       // [O,C]
    const float* __restrict__ w_prior)     // [O,C]
{
    int lane = threadIdx.x & 31;
    int wid  = threadIdx.x >> 5;
    int g    = lane >> 2;                  // 0..7  (mma groupID)
    int t    = lane & 3;                   // 0..3  (thread-in-group)

    // --- B fragments: B[k=c][n=o] = W[o][c], col-major k16n8.
    // Lane (g,t): b0 = {W[o][2t], W[o][2t+1]}, b1 = {W[o][2t+8], W[o][2t+9]},
    // with o = g (lo outputs) or g+8 (hi outputs).
    const float2* wo2 = (const float2*)w_obj;
    const float2* wp2 = (const float2*)w_prior;
    float2 f;
    unsigned bo_lo0, bo_lo1, bo_hi0, bo_hi1, bp_lo0, bp_lo1, bp_hi0, bp_hi1;
    f = __ldg(&wo2[g * 8 + t]);           bo_lo0 = f2h2(f.x, f.y);
    f = __ldg(&wo2[g * 8 + 4 + t]);       bo_lo1 = f2h2(f.x, f.y);
    f = __ldg(&wo2[(g + 8) * 8 + t]);     bo_hi0 = f2h2(f.x, f.y);
    f = __ldg(&wo2[(g + 8) * 8 + 4 + t]); bo_hi1 = f2h2(f.x, f.y);
    f = __ldg(&wp2[g * 8 + t]);           bp_lo0 = f2h2(ALPHA_PRIOR * f.x, ALPHA_PRIOR * f.y);
    f = __ldg(&wp2[g * 8 + 4 + t]);       bp_lo1 = f2h2(ALPHA_PRIOR * f.x, ALPHA_PRIOR * f.y);
    f = __ldg(&wp2[(g + 8) * 8 + t]);     bp_hi0 = f2h2(ALPHA_PRIOR * f.x, ALPHA_PRIOR * f.y);
    f = __ldg(&wp2[(g + 8) * 8 + 4 + t]); bp_hi1 = f2h2(ALPHA_PRIOR * f.x, ALPHA_PRIOR * f.y);

    const float2* f2p = (const float2*)node_feat;   // f2p[n*8 + c/2]
    unsigned* yv = (unsigned*)g_y;                  // yv[n*8 + c/2]

    int warp_global = blockIdx.x * (TBLK / 32) + wid;

    for (int it = 0; it < GITER; it++) {
        int base = (warp_global * GITER + it) * 16;     // first node of group

        // --- A fragment: rows = nodes base+g / base+g+8, cols = feats.
        unsigned a[4];
        f = __ldg(&f2p[(size_t)(base + g)     * 8 + t]);     a[0] = f2h2(f.x, f.y);
        f = __ldg(&f2p[(size_t)(base + g + 8) * 8 + t]);     a[1] = f2h2(f.x, f.y);
        f = __ldg(&f2p[(size_t)(base + g)     * 8 + 4 + t]); a[2] = f2h2(f.x, f.y);
        f = __ldg(&f2p[(size_t)(base + g + 8) * 8 + 4 + t]); a[3] = f2h2(f.x, f.y);

        float dol[4], doh[4], dpl[4], dph[4];
        mma16816(dol, a, bo_lo0, bo_lo1);   // obj, outputs 0-7
        mma16816(doh, a, bo_hi0, bo_hi1);   // obj, outputs 8-15
        mma16816(dpl, a, bp_lo0, bp_lo1);   // prior, outputs 0-7
        mma16816(dph, a, bp_hi0, bp_hi1);   // prior, outputs 8-15

        // --- per-row type select + pack + store.
        // D layout: d[0],d[1] = row (base+g),   cols 2t, 2t+1
        //           d[2],d[3] = row (base+g+8), cols 2t, 2t+1
        int t0 = __ldg(&node_types[base + g])     & 1;
        int t1 = __ldg(&node_types[base + g + 8]) & 1;

        unsigned hlo0 = f2h2(t0 ? dpl[0] : dol[0], t0 ? dpl[1] : dol[1]);
        unsigned hhi0 = f2h2(t0 ? dph[0] : doh[0], t0 ? dph[1] : doh[1]);
        unsigned hlo1 = f2h2(t1 ? dpl[2] : dol[2], t1 ? dpl[3] : dol[3]);
        unsigned hhi1 = f2h2(t1 ? dph[2] : doh[2], t1 ? dph[3] : doh[3]);

        yv[(size_t)(base + g)     * 8 + t]     = hlo0;   // ch 2t,2t+1
        yv[(size_t)(base + g)     * 8 + 4 + t] = hhi0;   // ch 2t+8,2t+9
        yv[(size_t)(base + g + 8) * 8 + t]     = hlo1;
        yv[(size_t)(base + g + 8) * 8 + 4 + t] = hhi1;
    }

    // Fused grid zeroing (L2-absorbed; completes before splat via kernel boundary).
    uint4* gz = (uint4*)g_grid;
    const uint4 z = make_uint4(0u, 0u, 0u, 0u);
    for (size_t i = (size_t)blockIdx.x * TBLK + threadIdx.x; i < GRID_U4;
         i += (size_t)TGRID * TBLK)
        gz[i] = z;
}

// ---------------------------------------------------------------------------
// Kernel 2: splat — coalesced 32B reload of transformed values, 2x red.v4.f16x2
// into the pixel grid (L2-hit atomics).
// ---------------------------------------------------------------------------
__global__ __launch_bounds__(256) void splat_kernel(
    const float* __restrict__ node_xy)     // [B,K,2]
{
    int n = blockIdx.x * 256 + threadIdx.x;
    if (n >= NNODES) return;
    int b = n / KK;

    float2 xy = ((const float2*)node_xy)[n];
    // jnp.round == round-half-to-even == rintf; clip to [0, 511]
    int ix = (int)fminf(fmaxf(rintf(xy.x), 0.f), (float)(WW - 1));
    int iy = (int)fminf(fmaxf(rintf(xy.y), 0.f), (float)(HH - 1));
    int pix = iy * WW + ix;

    const uint4* yv = (const uint4*)g_y;
    uint4 y0 = __ldg(&yv[(size_t)n * 2 + 0]);   // ch 0-7
    uint4 y1 = __ldg(&yv[(size_t)n * 2 + 1]);   // ch 8-15
    uint4* d0 = &g_grid[0][b][pix];
    uint4* d1 = &g_grid[1][b][pix];
    asm volatile("red.global.add.noftz.v4.f16x2 [%0], {%1, %2, %3, %4};"
                 :: "l"(d0), "r"(y0.x), "r"(y0.y), "r"(y0.z), "r"(y0.w) : "memory");
    asm volatile("red.global.add.noftz.v4.f16x2 [%0], {%1, %2, %3, %4};"
                 :: "l"(d1), "r"(y1.x), "r"(y1.y), "r"(y1.z), "r"(y1.w) : "memory");
}

// ---------------------------------------------------------------------------
// Kernel 3: conv — depthwise 3x3 over fp16 half-planes (fp32 math), NCHW fp32
// writeout. Thread: one x, one channel-half (8 ch), strip of 4 y rows.
// Grid = (8, 128, 8) = 8192 blocks.
// ---------------------------------------------------------------------------
__global__ __launch_bounds__(128) void conv_kernel(float* __restrict__ out) {
    int lane = threadIdx.x & 31;
    int w    = threadIdx.x >> 5;               // 0..3
    int h    = w & 1;                          // channel-half
    int x    = blockIdx.x * 64 + (w >> 1) * 32 + lane;  // 0..511
    int y0   = blockIdx.y * 4;                 // strip start
    int b    = blockIdx.z;

    const uint4* plane = g_grid[h][b];
    const uint4 z16 = make_uint4(0u, 0u, 0u, 0u);

    float acc[4][8];
    #pragma unroll
    for (int j = 0; j < 4; j++)
        #pragma unroll
        for (int i = 0; i < 8; i++) acc[j][i] = 0.f;

    #pragma unroll
    for (int r = 0; r < 6; r++) {
        int yy = y0 - 1 + r;
        if ((unsigned)yy >= HH) continue;      // y zero-pad

        const uint4* row = plane + (size_t)yy * WW;
        uint4 cq = __ldg(row + x);
        uint4 lq = (x > 0)      ? __ldg(row + x - 1) : z16;
        uint4 rq = (x < WW - 1) ? __ldg(row + x + 1) : z16;

        const __half2* ch = (const __half2*)&cq;
        const __half2* lh = (const __half2*)&lq;
        const __half2* rh = (const __half2*)&rq;

        float u[8], v[8];
        #pragma unroll
        for (int j = 0; j < 4; j++) {
            float2 cf = __half22float2(ch[j]);
            float2 lf = __half22float2(lh[j]);
            float2 rf = __half22float2(rh[j]);
            float sx = lf.x + rf.x, sy = lf.y + rf.y;
            u[2*j+0] = 0.075f * sx + 0.125f * cf.x;
            u[2*j+1] = 0.075f * sy + 0.125f * cf.y;
            v[2*j+0] = 0.125f * sx + 0.300f * cf.x;
            v[2*j+1] = 0.125f * sy + 0.300f * cf.y;
        }

        #pragma unroll
        for (int j = 0; j < 4; j++) {
            int d = (r - 1) - j;               // input row offset from output row
            if (d == 0) {
                #pragma unroll
                for (int i = 0; i < 8; i++) acc[j][i] += v[i];
            } else if (d == 1 || d == -1) {
                #pragma unroll
                for (int i = 0; i < 8; i++) acc[j][i] += u[i];
            }
        }
    }

    // NCHW writeout: channels o = 8h..8h+7. Warp-coalesced streaming stores.
    const size_t plane_out = (size_t)HH * WW;
    size_t base = ((size_t)b * OO + h * 8) * plane_out + (size_t)y0 * WW + x;
    #pragma unroll
    for (int i = 0; i < 8; i++)
        #pragma unroll
        for (int j = 0; j < 4; j++)
            __stcs(&out[base + (size_t)i * plane_out + (size_t)j * WW], acc[j][i]);
}

// ---------------------------------------------------------------------------
// Launch: transform(+zero) -> splat -> conv. 3 launches total.
// Inputs: node_feat, node_xy, hw(int64, unused), node_types, w_obj, w_prior.
// ---------------------------------------------------------------------------
extern "C" void kernel_launch(void* const* d_in, const int* in_sizes, int n_in,
                              void* d_out, int out_size) {
    const float* node_feat  = (const float*)d_in[0];
    const float* node_xy    = (const float*)d_in[1];
    const int*   node_types = (const int*)d_in[3];
    const float* w_obj      = (const float*)d_in[4];
    const float* w_prior    = (const float*)d_in[5];
    float* out = (float*)d_out;

    transform_kernel<<<TGRID, TBLK>>>(node_feat, node_types, w_obj, w_prior);
    splat_kernel<<<(NNODES + 255) / 256, 256>>>(node_xy);
    dim3 conv_grid(WW / 64, HH / 4, BB);       // (8, 128, 8) = 8192 blocks
    conv_kernel<<<conv_grid, 128>>>(out);
}